// round 4
// baseline (speedup 1.0000x reference)
#include <cuda_runtime.h>
#include <cuda_bf16.h>

// DCN-v1 cross network, closed form:
//   x_l = input * A_l + cumB_l   (A scalar per row, cumB row-independent)
//   d_l = dot(input, w_l)        (per row)
//   c_l = dot(cumB_l, w_l)       (row-independent constant)
//   s_l = A_l * d_l + c_l ;  A_{l+1} = A_l + s_l ;  cumB_{l+1} = cumB_l + b_l
//   out = input * A_6 + cumB_6
//
// R3: no shared memory, no __syncthreads, input NOT register-resident.
// Dot pass streams input (DRAM); epilogue re-reads it (L1/L2 hit). W/Bsum/c
// are read via LDG and are L1-resident per SM. launch_bounds(256,4) caps
// regs at 64 -> 4 CTAs/SM for latency hiding.

#define CN_D       1024
#define CN_F4      256              // float4 per row
#define CN_L       6
#define CN_THREADS 256
#define CN_ROWS_PER_WARP 2
#define CN_ROWS_PER_BLOCK (8 * CN_ROWS_PER_WARP)   // 16

__device__ float  g_c[CN_L];
__device__ float4 g_bsum[CN_F4];

// ---------------------------------------------------------------------------
// Precompute c[l] = dot(cumB_l, w_l) and Bsum = sum_l b_l. One block, 256 thr.
// ---------------------------------------------------------------------------
__global__ void cn_precompute(const float* __restrict__ W,
                              const float* __restrict__ bias)
{
    __shared__ float sred[8][CN_L];

    const int tid  = threadIdx.x;        // 0..255, one float4 of D each
    const int lane = tid & 31;
    const int warp = tid >> 5;

    const float4* W4 = (const float4*)W;
    const float4* B4 = (const float4*)bias;

    float4 cum = make_float4(0.f, 0.f, 0.f, 0.f);
    float cpart[CN_L];

    #pragma unroll
    for (int l = 0; l < CN_L; ++l) {
        float4 w = W4[l * CN_F4 + tid];
        cpart[l] = cum.x * w.x + cum.y * w.y + cum.z * w.z + cum.w * w.w;
        float4 b = B4[l * CN_F4 + tid];
        cum.x += b.x; cum.y += b.y; cum.z += b.z; cum.w += b.w;
    }

    #pragma unroll
    for (int l = 0; l < CN_L; ++l) {
        float v = cpart[l];
        v += __shfl_xor_sync(0xFFFFFFFFu, v, 16);
        v += __shfl_xor_sync(0xFFFFFFFFu, v, 8);
        v += __shfl_xor_sync(0xFFFFFFFFu, v, 4);
        v += __shfl_xor_sync(0xFFFFFFFFu, v, 2);
        v += __shfl_xor_sync(0xFFFFFFFFu, v, 1);
        if (lane == 0) sred[warp][l] = v;
    }
    __syncthreads();

    if (warp == 0 && lane < CN_L) {
        float v = 0.f;
        #pragma unroll
        for (int w = 0; w < 8; ++w) v += sred[w][lane];
        g_c[lane] = v;
    }

    g_bsum[tid] = cum;
}

// ---------------------------------------------------------------------------
// Main kernel: 2 rows per warp, 16 rows per block, no smem, no barriers.
// ---------------------------------------------------------------------------
__global__ __launch_bounds__(CN_THREADS, 4)
void cn_main(const float* __restrict__ inp,
             const float* __restrict__ W,
             float* __restrict__ out)
{
    const int tid  = threadIdx.x;
    const int lane = tid & 31;
    const int warp = tid >> 5;

    const size_t row0 = (size_t)blockIdx.x * CN_ROWS_PER_BLOCK
                      + (size_t)warp * CN_ROWS_PER_WARP;

    const float4* __restrict__ rinA = (const float4*)(inp + row0 * CN_D);
    const float4* __restrict__ rinB = (const float4*)(inp + (row0 + 1) * CN_D);
    const float4* __restrict__ W4   = (const float4*)W;

    // 12 simultaneous dot products (6 layers x 2 rows), streaming the input.
    float acc[2][CN_L];
    #pragma unroll
    for (int l = 0; l < CN_L; ++l) { acc[0][l] = 0.f; acc[1][l] = 0.f; }

    #pragma unroll
    for (int j = 0; j < 8; ++j) {
        const int col = j * 32 + lane;
        float4 a4 = rinA[col];
        float4 b4 = rinB[col];
        #pragma unroll
        for (int l = 0; l < CN_L; ++l) {
            float4 w = W4[l * CN_F4 + col];
            float a = acc[0][l];
            a = fmaf(a4.x, w.x, a);
            a = fmaf(a4.y, w.y, a);
            a = fmaf(a4.z, w.z, a);
            a = fmaf(a4.w, w.w, a);
            acc[0][l] = a;
            float b = acc[1][l];
            b = fmaf(b4.x, w.x, b);
            b = fmaf(b4.y, w.y, b);
            b = fmaf(b4.z, w.z, b);
            b = fmaf(b4.w, w.w, b);
            acc[1][l] = b;
        }
    }

    // Butterfly-reduce all 12 scalars (every lane ends with the full sum).
    #pragma unroll
    for (int r = 0; r < 2; ++r) {
        #pragma unroll
        for (int l = 0; l < CN_L; ++l) {
            float v = acc[r][l];
            v += __shfl_xor_sync(0xFFFFFFFFu, v, 16);
            v += __shfl_xor_sync(0xFFFFFFFFu, v, 8);
            v += __shfl_xor_sync(0xFFFFFFFFu, v, 4);
            v += __shfl_xor_sync(0xFFFFFFFFu, v, 2);
            v += __shfl_xor_sync(0xFFFFFFFFu, v, 1);
            acc[r][l] = v;
        }
    }

    // Scalar recurrence: A_{l+1} = A_l + (A_l * d_l + c_l)
    float A0 = 1.f, A1 = 1.f;
    #pragma unroll
    for (int l = 0; l < CN_L; ++l) {
        float cl = g_c[l];
        A0 += fmaf(A0, acc[0][l], cl);
        A1 += fmaf(A1, acc[1][l], cl);
    }

    // out = input * A + Bsum  (input re-read: L1/L2 hit; Bsum L1-resident)
    float4* __restrict__ routA = (float4*)(out + row0 * CN_D);
    float4* __restrict__ routB = (float4*)(out + (row0 + 1) * CN_D);
    #pragma unroll
    for (int j = 0; j < 8; ++j) {
        const int col = j * 32 + lane;
        float4 bs = g_bsum[col];
        float4 a4 = rinA[col];
        float4 b4 = rinB[col];
        float4 oa, ob;
        oa.x = fmaf(a4.x, A0, bs.x);
        oa.y = fmaf(a4.y, A0, bs.y);
        oa.z = fmaf(a4.z, A0, bs.z);
        oa.w = fmaf(a4.w, A0, bs.w);
        ob.x = fmaf(b4.x, A1, bs.x);
        ob.y = fmaf(b4.y, A1, bs.y);
        ob.z = fmaf(b4.z, A1, bs.z);
        ob.w = fmaf(b4.w, A1, bs.w);
        routA[col] = oa;
        routB[col] = ob;
    }
}

extern "C" void kernel_launch(void* const* d_in, const int* in_sizes, int n_in,
                              void* d_out, int out_size)
{
    const float* inp  = (const float*)d_in[0];   // [B, D]
    const float* W    = (const float*)d_in[1];   // [L, D]
    const float* bias = (const float*)d_in[2];   // [L, D]
    float* out        = (float*)d_out;           // [B, D]

    const int B = in_sizes[0] / CN_D;                    // 16384
    const int blocks = B / CN_ROWS_PER_BLOCK;            // 1024

    cn_precompute<<<1, CN_THREADS>>>(W, bias);
    cn_main<<<blocks, CN_THREADS>>>(inp, W, out);
}